// round 16
// baseline (speedup 1.0000x reference)
#include <cuda_runtime.h>
#include <cuda_fp16.h>
#include <math.h>
#include <stdint.h>

// Problem constants
#define BB 2
#define SS 2048
#define DM 1024
#define NH 16
#define HD 64
#define MROWS (BB*SS)        // 4096

// Scratch (device globals; no allocations allowed)
__device__ __half g_xh[MROWS*DM];      // fp16 x            [m][k]
__device__ __half g_Wt[4*DM*DM];       // fp16 W^T          [n][k] x4
__device__ __half g_Qh[BB*NH*SS*HD];   // [b,h,s,d] fp16
__device__ __half g_Kh[BB*NH*SS*HD];   // [b,h,s,d] fp16
__device__ __half g_Vt[BB*NH*HD*SS];   // [b,h,d,s] fp16 (transposed)
__device__ __half g_att[BB*SS*DM];     // [b,s, h*64+d] fp16

// ---------------------------------------------------------------------------
// helpers
// ---------------------------------------------------------------------------
__device__ __forceinline__ void mma_f16(float c[4],
    uint32_t a0, uint32_t a1, uint32_t a2, uint32_t a3,
    uint32_t b0, uint32_t b1)
{
    asm volatile(
        "mma.sync.aligned.m16n8k16.row.col.f32.f16.f16.f32 "
        "{%0,%1,%2,%3}, {%4,%5,%6,%7}, {%8,%9}, {%0,%1,%2,%3};"
        : "+f"(c[0]), "+f"(c[1]), "+f"(c[2]), "+f"(c[3])
        : "r"(a0), "r"(a1), "r"(a2), "r"(a3), "r"(b0), "r"(b1));
}

__device__ __forceinline__ uint32_t smem_u32(const void* p) {
    uint32_t a;
    asm("{ .reg .u64 t; cvta.to.shared.u64 t, %1; cvt.u32.u64 %0, t; }"
        : "=r"(a) : "l"(p));
    return a;
}

__device__ __forceinline__ uint32_t ex2_f16x2(uint32_t x) {
    uint32_t y;
    asm("ex2.approx.f16x2 %0, %1;" : "=r"(y) : "r"(x));
    return y;
}

#define LDSM4(r0, r1, r2, r3, addr) \
    asm volatile("ldmatrix.sync.aligned.m8n8.x4.shared.b16 {%0,%1,%2,%3}, [%4];" \
                 : "=r"(r0), "=r"(r1), "=r"(r2), "=r"(r3) : "r"(addr))

#define CP16(dst, src) \
    asm volatile("cp.async.cg.shared.global [%0], [%1], 16;\n" \
                 :: "r"(dst), "l"(src))
#define CP_COMMIT() asm volatile("cp.async.commit_group;\n")
#define CP_WAIT0()  asm volatile("cp.async.wait_group 0;\n")
#define CP_WAIT1()  asm volatile("cp.async.wait_group 1;\n")

// ---------------------------------------------------------------------------
// prep: x -> fp16 (same layout); W -> fp16 transposed [n][k]
// ---------------------------------------------------------------------------
__global__ __launch_bounds__(256) void cvt_x_h(const float* __restrict__ s,
                                               __half* __restrict__ d)
{
    int i = (blockIdx.x * 256 + threadIdx.x) * 4;
    float4 v = *(const float4*)(s + i);
    *(__half2*)(d + i)     = __floats2half2_rn(v.x, v.y);
    *(__half2*)(d + i + 2) = __floats2half2_rn(v.z, v.w);
}

__global__ __launch_bounds__(256) void cvt_w_t(
    const float* __restrict__ w0, const float* __restrict__ w1,
    const float* __restrict__ w2, const float* __restrict__ w3,
    __half* __restrict__ d)
{
    __shared__ float t[32][33];
    const int z = blockIdx.z;
    const float* s = (z == 0) ? w0 : (z == 1) ? w1 : (z == 2) ? w2 : w3;
    const int k0 = blockIdx.y * 32;
    const int n0 = blockIdx.x * 32;
    const int tx = threadIdx.x & 31;
    const int ty = threadIdx.x >> 5;     // 0..7
    #pragma unroll
    for (int i = 0; i < 4; i++)
        t[ty + 8 * i][tx] = s[(size_t)(k0 + ty + 8 * i) * DM + n0 + tx];
    __syncthreads();
    __half* dz = d + (size_t)z * DM * DM;
    #pragma unroll
    for (int i = 0; i < 4; i++)
        dz[(size_t)(n0 + ty + 8 * i) * DM + k0 + tx] =
            __float2half_rn(t[tx][ty + 8 * i]);
}

// ---------------------------------------------------------------------------
// 3-stage cp.async fp16 GEMM body, ldmatrix fragments.  (R13, proven)
// A fp16 [m][k]; Wt fp16 [n][k]. 128x128 tile, BK=64, m16n8k16, fp32 accum.
// OUTMODE: 0 = fp32 row-major; 1 = fp16 [b,h,s,d]; 2 = fp16 [b,h,d,s].
// ---------------------------------------------------------------------------
#define GSTAGES 3
#define GBK 64
#define HST 72                   // halves per smem row (64 + 8 pad)
#define STAGE_H (128*HST)        // halves per A or B stage (9216)
#define GEMM_SMEM (GSTAGES*2*STAGE_H*2)   // 110592 B
#define GNT (DM/GBK)             // 16 k-tiles

template<int OUTMODE>
__device__ __forceinline__ void gemm_body(
    const __half* __restrict__ A, const __half* __restrict__ Wt,
    const float* __restrict__ bias, void* __restrict__ Cv)
{
    extern __shared__ __half smh[];
    // layout: A0 | A1 | A2 | B0 | B1 | B2

    const int tid  = threadIdx.x;
    const int warp = tid >> 5;
    const int lane = tid & 31;
    const int wm   = (warp >> 2) * 64;
    const int wn   = (warp & 3) * 32;
    const int row0 = blockIdx.y * 128;
    const int col0 = blockIdx.x * 128;
    const int fr   = lane >> 2;
    const int fk   = lane & 3;
    const int g    = lane >> 3;      // ldmatrix address group 0..3
    const int rr   = lane & 7;

    const uint32_t sbase = smem_u32(smh);

    uint32_t aoff[4], boff[2];
    #pragma unroll
    for (int mi = 0; mi < 4; mi++)
        aoff[mi] = (uint32_t)((wm + mi * 16 + ((g & 1) << 3) + rr) * HST
                              + ((g >> 1) << 3)) * 2;
    #pragma unroll
    for (int p = 0; p < 2; p++)
        boff[p] = (uint32_t)((wn + p * 16 + ((g >> 1) << 3) + rr) * HST
                             + ((g & 1) << 3)) * 2;

    float acc[4][4][4];
    #pragma unroll
    for (int i = 0; i < 4; i++)
        #pragma unroll
        for (int j = 0; j < 4; j++)
            #pragma unroll
            for (int r = 0; r < 4; r++) acc[i][j][r] = 0.f;

    #define G_ISSUE(kt, s) do {                                              \
        uint32_t abase = sbase + (uint32_t)(s) * (STAGE_H * 2);              \
        uint32_t bbase = sbase + (uint32_t)((GSTAGES + (s)) * STAGE_H) * 2;  \
        _Pragma("unroll")                                                    \
        for (int i = 0; i < 4; i++) {                                        \
            int chunk = tid + 256 * i;                                       \
            int row  = chunk >> 3;                                           \
            int coff = (chunk & 7) * 8;                                      \
            CP16(abase + (uint32_t)(row * HST + coff) * 2,                   \
                 A  + (size_t)(row0 + row) * DM + (kt) * GBK + coff);        \
            CP16(bbase + (uint32_t)(row * HST + coff) * 2,                   \
                 Wt + (size_t)(col0 + row) * DM + (kt) * GBK + coff);        \
        }                                                                    \
        CP_COMMIT();                                                         \
    } while (0)

    G_ISSUE(0, 0);
    G_ISSUE(1, 1);

    for (int kt = 0; kt < GNT; kt++) {
        const int cur = kt % GSTAGES;
        CP_WAIT1();
        __syncthreads();
        if (kt + 2 < GNT) {
            G_ISSUE(kt + 2, (kt + 2) % GSTAGES);
        } else {
            CP_COMMIT();
        }

        const uint32_t abase = sbase + (uint32_t)cur * (STAGE_H * 2);
        const uint32_t bbase = sbase + (uint32_t)((GSTAGES + cur) * STAGE_H) * 2;

        #pragma unroll
        for (int ks = 0; ks < 4; ks++) {     // 4 k-steps of 16
            uint32_t af[4][4];
            uint32_t bf[2][4];
            #pragma unroll
            for (int mi = 0; mi < 4; mi++)
                LDSM4(af[mi][0], af[mi][1], af[mi][2], af[mi][3],
                      abase + aoff[mi] + 32 * ks);
            #pragma unroll
            for (int p = 0; p < 2; p++)
                LDSM4(bf[p][0], bf[p][1], bf[p][2], bf[p][3],
                      bbase + boff[p] + 32 * ks);
            #pragma unroll
            for (int mi = 0; mi < 4; mi++)
                #pragma unroll
                for (int ni = 0; ni < 4; ni++)
                    mma_f16(acc[mi][ni],
                            af[mi][0], af[mi][1], af[mi][2], af[mi][3],
                            bf[ni >> 1][(ni & 1) * 2],
                            bf[ni >> 1][(ni & 1) * 2 + 1]);
        }
    }

    // ---- epilogue ----
    #pragma unroll
    for (int mi = 0; mi < 4; mi++) {
        int r = row0 + wm + mi * 16 + fr;
        #pragma unroll
        for (int ni = 0; ni < 4; ni++) {
            int c = col0 + wn + ni * 8 + 2 * fk;
            float bb0 = bias[c], bb1 = bias[c + 1];
            float v0 = acc[mi][ni][0] + bb0, v1 = acc[mi][ni][1] + bb1;
            float v2 = acc[mi][ni][2] + bb0, v3 = acc[mi][ni][3] + bb1;
            if (OUTMODE == 0) {
                float* C = (float*)Cv;
                *(float2*)&C[(size_t)r * DM + c]       = make_float2(v0, v1);
                *(float2*)&C[(size_t)(r + 8) * DM + c] = make_float2(v2, v3);
            } else if (OUTMODE == 1) {
                __half* C = (__half*)Cv;
                int h = c >> 6, d = c & 63;
                int b0i = r >> 11, s0 = r & 2047;
                size_t i0 = ((((size_t)b0i * NH + h) * SS + s0) * HD) + d;
                *(__half2*)&C[i0] = __floats2half2_rn(v0, v1);
                int r2 = r + 8;
                int b1i = r2 >> 11, s1 = r2 & 2047;
                size_t i1 = ((((size_t)b1i * NH + h) * SS + s1) * HD) + d;
                *(__half2*)&C[i1] = __floats2half2_rn(v2, v3);
            } else {
                __half* C = (__half*)Cv;       // [b,h,d,s]
                int h = c >> 6, d = c & 63;
                int b0i = r >> 11, s0 = r & 2047;
                int r2 = r + 8;
                int b1i = r2 >> 11, s1 = r2 & 2047;
                size_t base0 = (((size_t)b0i * NH + h) * HD);
                size_t base1 = (((size_t)b1i * NH + h) * HD);
                C[(base0 + d    ) * SS + s0] = __float2half_rn(v0);
                C[(base0 + d + 1) * SS + s0] = __float2half_rn(v1);
                C[(base1 + d    ) * SS + s1] = __float2half_rn(v2);
                C[(base1 + d + 1) * SS + s1] = __float2half_rn(v3);
            }
        }
    }
    #undef G_ISSUE
}

__global__ __launch_bounds__(256, 2) void gemm_qkv(
    const __half* __restrict__ A, const __half* __restrict__ Wt,
    const float* __restrict__ b0, const float* __restrict__ b1,
    const float* __restrict__ b2,
    __half* __restrict__ C0, __half* __restrict__ C1, __half* __restrict__ C2)
{
    const int z = blockIdx.z;
    const __half* W = Wt + (size_t)z * DM * DM;
    if (z == 2) {
        gemm_body<2>(A, W, b2, C2);
    } else {
        gemm_body<1>(A, W, z ? b1 : b0, z ? C1 : C0);
    }
}

__global__ __launch_bounds__(256, 2) void gemm_o(
    const __half* __restrict__ A, const __half* __restrict__ Wt,
    const float* __restrict__ bias, float* __restrict__ C)
{
    gemm_body<0>(A, Wt, bias, C);
}

// ---------------------------------------------------------------------------
// fp16 flash attention (causal), m16n8k16, fp32 accum. R16:
//  - paired q-tiles (R15, constant 17-stage work per block, one wave)
//  - DEFERRED PV: stage order QK_t -> rescale+PV_{t-1} -> softmax_t, so the
//    tensor pipe executes PV of the previous stage while scalar softmax runs
//  - 3-stage K/V smem ring (55 KB) with WAIT1; per-pass 2-stage prologue
//  - values/order per row unchanged -> bitwise-identical output
// ---------------------------------------------------------------------------
#define ABQ 128
#define LKEYS 64
#define HSTR 72
#define KSTAGE_H (LKEYS*HSTR)
#define KSTAGE_B (KSTAGE_H*2)         // 9216 B per K or V stage
#define ATTN_SMEM (6*KSTAGE_B)        // K0..K2 | V0..V2 = 55296 B
#define NQT (SS/ABQ)                  // 16 q-tiles per (b,h)

__global__ __launch_bounds__(256, 2) void attn_h(
    const __half* __restrict__ Q, const __half* __restrict__ K,
    const __half* __restrict__ Vt, __half* __restrict__ O)
{
    extern __shared__ __half smh[];
    // layout: K stage0..2 | V stage0..2

    const int bh   = blockIdx.y;
    const int tid  = threadIdx.x;
    const int warp = tid >> 5;
    const int lane = tid & 31;
    const int fr   = lane >> 2;
    const int fk   = lane & 3;
    const int g    = lane >> 3;
    const int rr   = lane & 7;
    const int wrow = warp * 16;

    const __half* Qb  = Q  + (size_t)bh * SS * HD;
    const __half* Kb  = K  + (size_t)bh * SS * HD;
    const __half* Vtb = Vt + (size_t)bh * HD * SS;

    const float tsc = 0.18033688f;     // (1/sqrt(64)) * log2(e)

    uint32_t kvoff[4];
    #pragma unroll
    for (int p = 0; p < 4; p++)
        kvoff[p] = (uint32_t)((p * 16 + ((g >> 1) << 3) + rr) * HSTR
                              + ((g & 1) << 3)) * 2;

    const int crow = tid >> 3;           // 0..31
    const int coff = (tid & 7) * 8;      // halves
    const uint32_t sbase = smem_u32(smh);

    #define A_ISSUE(lt, s) do {                                              \
        const int kk0 = (lt) * LKEYS;                                        \
        uint32_t koff = sbase + (uint32_t)(s) * KSTAGE_B;                    \
        uint32_t voff = sbase + (uint32_t)(3 + (s)) * KSTAGE_B;              \
        _Pragma("unroll")                                                    \
        for (int i = 0; i < 2; i++) {                                        \
            int row = crow + 32 * i;                                         \
            CP16(koff + (uint32_t)(row * HSTR + coff) * 2,                   \
                 Kb + (size_t)(kk0 + row) * HD + coff);                      \
            CP16(voff + (uint32_t)(row * HSTR + coff) * 2,                   \
                 Vtb + (size_t)row * SS + kk0 + coff);                       \
        }                                                                    \
        CP_COMMIT();                                                         \
    } while (0)

    // PV of carried stage: rescale Oacc then mma against V in slot 'pb'
    #define DO_PV(pb) do {                                                   \
        const uint32_t vb = sbase + (uint32_t)(3 + (pb)) * KSTAGE_B;         \
        if (!__all_sync(0xFFFFFFFFu, (al0p == 1.f) & (al1p == 1.f))) {       \
            _Pragma("unroll")                                                \
            for (int nt = 0; nt < 8; nt++) {                                 \
                Oacc[nt][0] *= al0p; Oacc[nt][1] *= al0p;                    \
                Oacc[nt][2] *= al1p; Oacc[nt][3] *= al1p;                    \
            }                                                                \
        }                                                                    \
        _Pragma("unroll")                                                    \
        for (int kst = 0; kst < 4; kst++) {                                  \
            uint32_t vf[4][4];                                               \
            _Pragma("unroll")                                                \
            for (int p = 0; p < 4; p++)                                      \
                LDSM4(vf[p][0], vf[p][1], vf[p][2], vf[p][3],                \
                      vb + kvoff[p] + 32 * kst);                             \
            uint32_t a0 = P01p[2 * kst];                                     \
            uint32_t a1 = P23p[2 * kst];                                     \
            uint32_t a2 = P01p[2 * kst + 1];                                 \
            uint32_t a3 = P23p[2 * kst + 1];                                 \
            _Pragma("unroll")                                                \
            for (int nt = 0; nt < 8; nt++)                                   \
                mma_f16(Oacc[nt], a0, a1, a2, a3,                            \
                        vf[nt >> 1][(nt & 1) * 2],                           \
                        vf[nt >> 1][(nt & 1) * 2 + 1]);                      \
        }                                                                    \
    } while (0)

    // paired q-tiles: work(qb) + work(NQT-1-qb) = NQT+1 stages, constant
    #pragma unroll 1
    for (int pass = 0; pass < 2; pass++) {
        const int qb = pass ? (NQT - 1 - blockIdx.x) : blockIdx.x;
        const int q0 = qb * ABQ;

        __syncthreads();   // pass-boundary: prior drain-PV reads done before
                           // prologue overwrites slots

        uint32_t Qf[4][4];
        {
            const __half* qr0 = Qb + (size_t)(q0 + wrow + fr) * HD;
            const __half* qr1 = qr0 + 8 * HD;
            #pragma unroll
            for (int ks = 0; ks < 4; ks++) {
                Qf[ks][0] = *(const uint32_t*)(qr0 + 16 * ks + 2 * fk);
                Qf[ks][1] = *(const uint32_t*)(qr1 + 16 * ks + 2 * fk);
                Qf[ks][2] = *(const uint32_t*)(qr0 + 16 * ks + 8 + 2 * fk);
                Qf[ks][3] = *(const uint32_t*)(qr1 + 16 * ks + 8 + 2 * fk);
            }
        }

        float Oacc[8][4];
        #pragma unroll
        for (int nt = 0; nt < 8; nt++)
            #pragma unroll
            for (int r = 0; r < 4; r++) Oacc[nt][r] = 0.f;

        float m0 = -INFINITY, m1 = -INFINITY, l0 = 0.f, l1 = 0.f;
        float al0p = 1.f, al1p = 1.f;
        uint32_t P01p[8], P23p[8];
        bool prevActive = false;

        const int r0g = q0 + wrow + fr;
        const int r1g = r0g + 8;
        const int nload = (q0 + ABQ) / LKEYS;   // 2*qb + 2 >= 2

        A_ISSUE(0, 0);
        A_ISSUE(1, 1);

        for (int lt = 0; lt < nload; lt++) {
            const int k0  = lt * LKEYS;
            const int buf = lt % 3;
            CP_WAIT1();            // stage lt landed (stage lt+1 may pend)
            __syncthreads();

            const bool active = (k0 <= q0 + wrow + 15);   // warp-uniform
            const uint32_t kbase = sbase + (uint32_t)buf * KSTAGE_B;

            float Sacc[8][4];
            if (active) {
                // ---- S = Q K^T over 64 keys (queued first: feeds tensor) ----
                #pragma unroll
                for (int nt = 0; nt < 8; nt++)
                    #pragma unroll
                    for (int r = 0; r < 4; r++) Sacc[nt][r] = 0.f;
                #pragma unroll
                for (int ks = 0; ks < 4; ks++) {
                    uint32_t kf[4][4];
                    #pragma unroll
                    for (int p = 0; p < 4; p++)
                        LDSM4(kf[p][0], kf[p][1], kf[p][2], kf[p][3],
                              kbase + kvoff[p] + 32 * ks);
                    #pragma unroll
                    for (int nt = 0; nt < 8; nt++)
                        mma_f16(Sacc[nt],
                                Qf[ks][0], Qf[ks][1], Qf[ks][2], Qf[ks][3],
                                kf[nt >> 1][(nt & 1) * 2],
                                kf[nt >> 1][(nt & 1) * 2 + 1]);
                }
            }

            // ---- deferred PV of stage lt-1 (overlaps with softmax below) ----
            if (prevActive) DO_PV((lt + 2) % 3);   // (lt-1)%3 == (lt+2)%3

            if (active) {
                // ---- causal mask on raw S (only near diagonal) ----
                const bool full = (k0 + 63 <= q0 + wrow);  // warp-uniform
                if (!full) {
                    #pragma unroll
                    for (int nt = 0; nt < 8; nt++) {
                        int c0 = k0 + nt * 8 + 2 * fk;
                        if (c0     > r0g) Sacc[nt][0] = -INFINITY;
                        if (c0 + 1 > r0g) Sacc[nt][1] = -INFINITY;
                        if (c0     > r1g) Sacc[nt][2] = -INFINITY;
                        if (c0 + 1 > r1g) Sacc[nt][3] = -INFINITY;
                    }
                }

                float mx0 = Sacc[0][0], mx1 = Sacc[0][2];
                #pragma unroll
                for (int nt = 0; nt < 8; nt++) {
                    mx0 = fmaxf(mx0, fmaxf(Sacc[nt][0], Sacc[nt][1]));
                    mx1 = fmaxf(mx1, fmaxf(Sacc[nt][2], Sacc[nt][3]));
                }
                mx0 = fmaxf(mx0, __shfl_xor_sync(0xFFFFFFFFu, mx0, 1));
                mx0 = fmaxf(mx0, __shfl_xor_sync(0xFFFFFFFFu, mx0, 2));
                mx1 = fmaxf(mx1, __shfl_xor_sync(0xFFFFFFFFu, mx1, 1));
                mx1 = fmaxf(mx1, __shfl_xor_sync(0xFFFFFFFFu, mx1, 2));

                float mn0 = fmaxf(m0, mx0 * tsc);
                float mn1 = fmaxf(m1, mx1 * tsc);
                al0p = exp2f(m0 - mn0);
                al1p = exp2f(m1 - mn1);
                m0 = mn0; m1 = mn1;

                float ps0 = 0.f, ps1 = 0.f;
                #pragma unroll
                for (int nt = 0; nt < 8; nt++) {
                    float f0 = fmaf(Sacc[nt][0], tsc, -m0);
                    float f1 = fmaf(Sacc[nt][1], tsc, -m0);
                    float f2 = fmaf(Sacc[nt][2], tsc, -m1);
                    float f3 = fmaf(Sacc[nt][3], tsc, -m1);
                    __half2 e01 = __floats2half2_rn(f0, f1);
                    __half2 e23 = __floats2half2_rn(f2, f3);
                    uint32_t p01 = ex2_f16x2(*(const uint32_t*)&e01);
                    uint32_t p23 = ex2_f16x2(*(const uint32_t*)&e23);
                    P01p[nt] = p01;
                    P23p[nt] = p23;
                    float2 q01 = __half22float2(*(const __half2*)&p01);
                    float2 q23 = __half22float2(*(const __half2*)&p23);
                    ps0 += q01.x + q01.y;
                    ps1 += q23.x + q23.y;
                }
                ps0 += __shfl_xor_sync(0xFFFFFFFFu, ps0, 1);
                ps0 += __shfl_xor_sync(0xFFFFFFFFu, ps0, 2);
                ps1 += __shfl_xor_sync(0xFFFFFFFFu, ps1, 1);
                ps1 += __shfl_xor_sync(0xFFFFFFFFu, ps1, 2);
                l0 = l0 * al0p + ps0;
                l1 = l1 * al1p + ps1;
            }
            prevActive = active;

            __syncthreads();       // all warps done reading slot (lt-1)%3
            if (lt + 2 < nload) {
                A_ISSUE(lt + 2, (lt + 2) % 3);   // overwrites slot (lt-1)%3
            } else {
                CP_COMMIT();       // keep wait_group accounting uniform
            }
        }

        // ---- drain: PV of the final stage ----
        if (prevActive) DO_PV((nload - 1) % 3);

        // ---- epilogue: normalize, write fp16 [b, s, h*64+d] ----
        const int b = bh >> 4, h = bh & 15;
        const float inv0 = 1.f / l0;
        const float inv1 = 1.f / l1;
        __half* O0 = O + ((size_t)(b * SS + r0g)) * DM + h * HD;
        __half* O1 = O + ((size_t)(b * SS + r1g)) * DM + h * HD;
        #pragma unroll
        for (int nt = 0; nt < 8; nt++) {
            int d = nt * 8 + 2 * fk;
            *(__half2*)(O0 + d) = __floats2half2_rn(Oacc[nt][0] * inv0,
                                                    Oacc[nt][1] * inv0);
            *(__half2*)(O1 + d) = __floats2half2_rn(Oacc[nt][2] * inv1,
                                                    Oacc[nt][3] * inv1);
        }
    }
    #undef A_ISSUE
    #undef DO_PV
}

// ---------------------------------------------------------------------------
extern "C" void kernel_launch(void* const* d_in, const int* in_sizes, int n_in,
                              void* d_out, int out_size)
{
    const float* x  = (const float*)d_in[0];
    const float* Wq = (const float*)d_in[1];
    const float* bq = (const float*)d_in[2];
    const float* Wk = (const float*)d_in[3];
    const float* bk = (const float*)d_in[4];
    const float* Wv = (const float*)d_in[5];
    const float* bv = (const float*)d_in[6];
    const float* Wo = (const float*)d_in[7];
    const float* bo = (const float*)d_in[8];

    __half *xh, *wt, *qp, *kp, *vp, *ap;
    cudaGetSymbolAddress((void**)&xh, g_xh);
    cudaGetSymbolAddress((void**)&wt, g_Wt);
    cudaGetSymbolAddress((void**)&qp, g_Qh);
    cudaGetSymbolAddress((void**)&kp, g_Kh);
    cudaGetSymbolAddress((void**)&vp, g_Vt);
    cudaGetSymbolAddress((void**)&ap, g_att);

    cudaFuncSetAttribute(gemm_qkv,
        cudaFuncAttributeMaxDynamicSharedMemorySize, GEMM_SMEM);
    cudaFuncSetAttribute(gemm_o,
        cudaFuncAttributeMaxDynamicSharedMemorySize, GEMM_SMEM);
    cudaFuncSetAttribute(attn_h,
        cudaFuncAttributeMaxDynamicSharedMemorySize, ATTN_SMEM);

    // prep: fp16 conversions (+ weight transpose)
    cvt_x_h<<<MROWS * DM / 1024, 256>>>(x, xh);
    cvt_w_t<<<dim3(DM / 32, DM / 32, 4), 256>>>(Wq, Wk, Wv, Wo, wt);

    dim3 gqkv(DM / 128, MROWS / 128, 3);   // (8, 32, 3)
    gemm_qkv<<<gqkv, 256, GEMM_SMEM>>>(xh, wt, bq, bk, bv, qp, kp, vp);

    attn_h<<<dim3(NQT / 2, BB * NH), 256, ATTN_SMEM>>>(qp, kp, vp, ap);

    dim3 go(DM / 128, MROWS / 128);        // (8, 32)
    gemm_o<<<go, 256, GEMM_SMEM>>>(ap, wt + (size_t)3*DM*DM, bo, (float*)d_out);
}

// round 17
// speedup vs baseline: 1.0191x; 1.0191x over previous
#include <cuda_runtime.h>
#include <cuda_fp16.h>
#include <math.h>
#include <stdint.h>

// Problem constants
#define BB 2
#define SS 2048
#define DM 1024
#define NH 16
#define HD 64
#define MROWS (BB*SS)        // 4096

// Scratch (device globals; no allocations allowed)
__device__ __half g_xh[MROWS*DM];      // fp16 x            [m][k]
__device__ __half g_Wt[4*DM*DM];       // fp16 W^T          [n][k] x4
__device__ __half g_Qh[BB*NH*SS*HD];   // [b,h,s,d] fp16
__device__ __half g_Kh[BB*NH*SS*HD];   // [b,h,s,d] fp16
__device__ __half g_Vt[BB*NH*HD*SS];   // [b,h,d,s] fp16 (transposed)
__device__ __half g_att[BB*SS*DM];     // [b,s, h*64+d] fp16

// ---------------------------------------------------------------------------
// helpers
// ---------------------------------------------------------------------------
__device__ __forceinline__ void mma_f16(float c[4],
    uint32_t a0, uint32_t a1, uint32_t a2, uint32_t a3,
    uint32_t b0, uint32_t b1)
{
    asm volatile(
        "mma.sync.aligned.m16n8k16.row.col.f32.f16.f16.f32 "
        "{%0,%1,%2,%3}, {%4,%5,%6,%7}, {%8,%9}, {%0,%1,%2,%3};"
        : "+f"(c[0]), "+f"(c[1]), "+f"(c[2]), "+f"(c[3])
        : "r"(a0), "r"(a1), "r"(a2), "r"(a3), "r"(b0), "r"(b1));
}

__device__ __forceinline__ uint32_t smem_u32(const void* p) {
    uint32_t a;
    asm("{ .reg .u64 t; cvta.to.shared.u64 t, %1; cvt.u32.u64 %0, t; }"
        : "=r"(a) : "l"(p));
    return a;
}

__device__ __forceinline__ uint32_t ex2_f16x2(uint32_t x) {
    uint32_t y;
    asm("ex2.approx.f16x2 %0, %1;" : "=r"(y) : "r"(x));
    return y;
}

#define LDSM4(r0, r1, r2, r3, addr) \
    asm volatile("ldmatrix.sync.aligned.m8n8.x4.shared.b16 {%0,%1,%2,%3}, [%4];" \
                 : "=r"(r0), "=r"(r1), "=r"(r2), "=r"(r3) : "r"(addr))

#define CP16(dst, src) \
    asm volatile("cp.async.cg.shared.global [%0], [%1], 16;\n" \
                 :: "r"(dst), "l"(src))
#define CP_COMMIT() asm volatile("cp.async.commit_group;\n")
#define CP_WAIT0()  asm volatile("cp.async.wait_group 0;\n")
#define CP_WAIT1()  asm volatile("cp.async.wait_group 1;\n")

// ---------------------------------------------------------------------------
// prep (single launch): z=0..3 -> W_z transpose+fp16; z=4..7 -> x quarter z-4
// grid: (1024, 1, 8), 256 threads. Each plane handles 1M elements.
// ---------------------------------------------------------------------------
__global__ __launch_bounds__(256) void prep_all(
    const float* __restrict__ x,
    const float* __restrict__ w0, const float* __restrict__ w1,
    const float* __restrict__ w2, const float* __restrict__ w3,
    __half* __restrict__ dx, __half* __restrict__ dw)
{
    const int z = blockIdx.z;
    if (z >= 4) {
        // x conversion: quarter (z-4), 1M elems, 4 per thread
        size_t base = (size_t)(z - 4) * (MROWS * DM / 4);
        size_t i = base + ((size_t)blockIdx.x * 256 + threadIdx.x) * 4;
        float4 v = *(const float4*)(x + i);
        *(__half2*)(dx + i)     = __floats2half2_rn(v.x, v.y);
        *(__half2*)(dx + i + 2) = __floats2half2_rn(v.z, v.w);
        return;
    }
    // weight transpose: 32x32 tile per block; blockIdx.x = tile index (0..1023)
    __shared__ float t[32][33];
    const float* s = (z == 0) ? w0 : (z == 1) ? w1 : (z == 2) ? w2 : w3;
    const int nt32 = DM / 32;                 // 32 tiles per dim
    const int k0 = (blockIdx.x / nt32) * 32;
    const int n0 = (blockIdx.x % nt32) * 32;
    const int tx = threadIdx.x & 31;
    const int ty = threadIdx.x >> 5;          // 0..7
    #pragma unroll
    for (int i = 0; i < 4; i++)
        t[ty + 8 * i][tx] = s[(size_t)(k0 + ty + 8 * i) * DM + n0 + tx];
    __syncthreads();
    __half* dz = dw + (size_t)z * DM * DM;
    #pragma unroll
    for (int i = 0; i < 4; i++)
        dz[(size_t)(n0 + ty + 8 * i) * DM + k0 + tx] =
            __float2half_rn(t[tx][ty + 8 * i]);
}

// ---------------------------------------------------------------------------
// 3-stage cp.async fp16 GEMM body, ldmatrix fragments.  (R13/R15, proven)
// A fp16 [m][k]; Wt fp16 [n][k]. 128x128 tile, BK=64, m16n8k16, fp32 accum.
// OUTMODE: 0 = fp32 row-major; 1 = fp16 [b,h,s,d]; 2 = fp16 [b,h,d,s].
// ---------------------------------------------------------------------------
#define GSTAGES 3
#define GBK 64
#define HST 72                   // halves per smem row (64 + 8 pad)
#define STAGE_H (128*HST)        // halves per A or B stage (9216)
#define GEMM_SMEM (GSTAGES*2*STAGE_H*2)   // 110592 B
#define GNT (DM/GBK)             // 16 k-tiles

template<int OUTMODE>
__device__ __forceinline__ void gemm_body(
    const __half* __restrict__ A, const __half* __restrict__ Wt,
    const float* __restrict__ bias, void* __restrict__ Cv)
{
    extern __shared__ __half smh[];
    // layout: A0 | A1 | A2 | B0 | B1 | B2

    const int tid  = threadIdx.x;
    const int warp = tid >> 5;
    const int lane = tid & 31;
    const int wm   = (warp >> 2) * 64;
    const int wn   = (warp & 3) * 32;
    const int row0 = blockIdx.y * 128;
    const int col0 = blockIdx.x * 128;
    const int fr   = lane >> 2;
    const int fk   = lane & 3;
    const int g    = lane >> 3;      // ldmatrix address group 0..3
    const int rr   = lane & 7;

    const uint32_t sbase = smem_u32(smh);

    uint32_t aoff[4], boff[2];
    #pragma unroll
    for (int mi = 0; mi < 4; mi++)
        aoff[mi] = (uint32_t)((wm + mi * 16 + ((g & 1) << 3) + rr) * HST
                              + ((g >> 1) << 3)) * 2;
    #pragma unroll
    for (int p = 0; p < 2; p++)
        boff[p] = (uint32_t)((wn + p * 16 + ((g >> 1) << 3) + rr) * HST
                             + ((g & 1) << 3)) * 2;

    float acc[4][4][4];
    #pragma unroll
    for (int i = 0; i < 4; i++)
        #pragma unroll
        for (int j = 0; j < 4; j++)
            #pragma unroll
            for (int r = 0; r < 4; r++) acc[i][j][r] = 0.f;

    #define G_ISSUE(kt, s) do {                                              \
        uint32_t abase = sbase + (uint32_t)(s) * (STAGE_H * 2);              \
        uint32_t bbase = sbase + (uint32_t)((GSTAGES + (s)) * STAGE_H) * 2;  \
        _Pragma("unroll")                                                    \
        for (int i = 0; i < 4; i++) {                                        \
            int chunk = tid + 256 * i;                                       \
            int row  = chunk >> 3;                                           \
            int coff = (chunk & 7) * 8;                                      \
            CP16(abase + (uint32_t)(row * HST + coff) * 2,                   \
                 A  + (size_t)(row0 + row) * DM + (kt) * GBK + coff);        \
            CP16(bbase + (uint32_t)(row * HST + coff) * 2,                   \
                 Wt + (size_t)(col0 + row) * DM + (kt) * GBK + coff);        \
        }                                                                    \
        CP_COMMIT();                                                         \
    } while (0)

    G_ISSUE(0, 0);
    G_ISSUE(1, 1);

    for (int kt = 0; kt < GNT; kt++) {
        const int cur = kt % GSTAGES;
        CP_WAIT1();
        __syncthreads();
        if (kt + 2 < GNT) {
            G_ISSUE(kt + 2, (kt + 2) % GSTAGES);
        } else {
            CP_COMMIT();
        }

        const uint32_t abase = sbase + (uint32_t)cur * (STAGE_H * 2);
        const uint32_t bbase = sbase + (uint32_t)((GSTAGES + cur) * STAGE_H) * 2;

        #pragma unroll
        for (int ks = 0; ks < 4; ks++) {     // 4 k-steps of 16
            uint32_t af[4][4];
            uint32_t bf[2][4];
            #pragma unroll
            for (int mi = 0; mi < 4; mi++)
                LDSM4(af[mi][0], af[mi][1], af[mi][2], af[mi][3],
                      abase + aoff[mi] + 32 * ks);
            #pragma unroll
            for (int p = 0; p < 2; p++)
                LDSM4(bf[p][0], bf[p][1], bf[p][2], bf[p][3],
                      bbase + boff[p] + 32 * ks);
            #pragma unroll
            for (int mi = 0; mi < 4; mi++)
                #pragma unroll
                for (int ni = 0; ni < 4; ni++)
                    mma_f16(acc[mi][ni],
                            af[mi][0], af[mi][1], af[mi][2], af[mi][3],
                            bf[ni >> 1][(ni & 1) * 2],
                            bf[ni >> 1][(ni & 1) * 2 + 1]);
        }
    }

    // ---- epilogue ----
    #pragma unroll
    for (int mi = 0; mi < 4; mi++) {
        int r = row0 + wm + mi * 16 + fr;
        #pragma unroll
        for (int ni = 0; ni < 4; ni++) {
            int c = col0 + wn + ni * 8 + 2 * fk;
            float bb0 = bias[c], bb1 = bias[c + 1];
            float v0 = acc[mi][ni][0] + bb0, v1 = acc[mi][ni][1] + bb1;
            float v2 = acc[mi][ni][2] + bb0, v3 = acc[mi][ni][3] + bb1;
            if (OUTMODE == 0) {
                float* C = (float*)Cv;
                *(float2*)&C[(size_t)r * DM + c]       = make_float2(v0, v1);
                *(float2*)&C[(size_t)(r + 8) * DM + c] = make_float2(v2, v3);
            } else if (OUTMODE == 1) {
                __half* C = (__half*)Cv;
                int h = c >> 6, d = c & 63;
                int b0i = r >> 11, s0 = r & 2047;
                size_t i0 = ((((size_t)b0i * NH + h) * SS + s0) * HD) + d;
                *(__half2*)&C[i0] = __floats2half2_rn(v0, v1);
                int r2 = r + 8;
                int b1i = r2 >> 11, s1 = r2 & 2047;
                size_t i1 = ((((size_t)b1i * NH + h) * SS + s1) * HD) + d;
                *(__half2*)&C[i1] = __floats2half2_rn(v2, v3);
            } else {
                __half* C = (__half*)Cv;       // [b,h,d,s]
                int h = c >> 6, d = c & 63;
                int b0i = r >> 11, s0 = r & 2047;
                int r2 = r + 8;
                int b1i = r2 >> 11, s1 = r2 & 2047;
                size_t base0 = (((size_t)b0i * NH + h) * HD);
                size_t base1 = (((size_t)b1i * NH + h) * HD);
                C[(base0 + d    ) * SS + s0] = __float2half_rn(v0);
                C[(base0 + d + 1) * SS + s0] = __float2half_rn(v1);
                C[(base1 + d    ) * SS + s1] = __float2half_rn(v2);
                C[(base1 + d + 1) * SS + s1] = __float2half_rn(v3);
            }
        }
    }
    #undef G_ISSUE
}

__global__ __launch_bounds__(256, 2) void gemm_qkv(
    const __half* __restrict__ A, const __half* __restrict__ Wt,
    const float* __restrict__ b0, const float* __restrict__ b1,
    const float* __restrict__ b2,
    __half* __restrict__ C0, __half* __restrict__ C1, __half* __restrict__ C2)
{
    const int z = blockIdx.z;
    const __half* W = Wt + (size_t)z * DM * DM;
    if (z == 2) {
        gemm_body<2>(A, W, b2, C2);
    } else {
        gemm_body<1>(A, W, z ? b1 : b0, z ? C1 : C0);
    }
}

__global__ __launch_bounds__(256, 2) void gemm_o(
    const __half* __restrict__ A, const __half* __restrict__ Wt,
    const float* __restrict__ bias, float* __restrict__ C)
{
    gemm_body<0>(A, Wt, bias, C);
}

// ---------------------------------------------------------------------------
// fp16 flash attention (causal), m16n8k16, fp32 accum. R15 exact revert:
//  - paired q-tiles (qb, NQT-1-qb): constant 17-stage work, one balanced wave
//  - ldmatrix.x4 fragments, ex2.f16x2 softmax, 2-stage cp.async K/V
// ---------------------------------------------------------------------------
#define ABQ 128
#define LKEYS 64
#define HSTR 72
#define KSTAGE_H (LKEYS*HSTR)
#define ATTN_SMEM (4*KSTAGE_H*2)      // 36864 B
#define NQT (SS/ABQ)                  // 16 q-tiles per (b,h)

__global__ __launch_bounds__(256, 2) void attn_h(
    const __half* __restrict__ Q, const __half* __restrict__ K,
    const __half* __restrict__ Vt, __half* __restrict__ O)
{
    extern __shared__ __half smh[];
    // layout: K stage0 | K stage1 | V stage0 | V stage1

    const int bh   = blockIdx.y;
    const int tid  = threadIdx.x;
    const int warp = tid >> 5;
    const int lane = tid & 31;
    const int fr   = lane >> 2;
    const int fk   = lane & 3;
    const int g    = lane >> 3;
    const int rr   = lane & 7;
    const int wrow = warp * 16;

    const __half* Qb  = Q  + (size_t)bh * SS * HD;
    const __half* Kb  = K  + (size_t)bh * SS * HD;
    const __half* Vtb = Vt + (size_t)bh * HD * SS;

    const float tsc = 0.18033688f;     // (1/sqrt(64)) * log2(e)

    uint32_t kvoff[4];
    #pragma unroll
    for (int p = 0; p < 4; p++)
        kvoff[p] = (uint32_t)((p * 16 + ((g >> 1) << 3) + rr) * HSTR
                              + ((g & 1) << 3)) * 2;

    const int crow = tid >> 3;           // 0..31
    const int coff = (tid & 7) * 8;      // halves
    const uint32_t sbase = smem_u32(smh);

    #define A_ISSUE(lt, s) do {                                              \
        const int kk0 = (lt) * LKEYS;                                        \
        uint32_t koff = sbase + (uint32_t)(s) * (KSTAGE_H * 2);              \
        uint32_t voff = sbase + (uint32_t)((2 + (s)) * KSTAGE_H) * 2;        \
        _Pragma("unroll")                                                    \
        for (int i = 0; i < 2; i++) {                                        \
            int row = crow + 32 * i;                                         \
            CP16(koff + (uint32_t)(row * HSTR + coff) * 2,                   \
                 Kb + (size_t)(kk0 + row) * HD + coff);                      \
            CP16(voff + (uint32_t)(row * HSTR + coff) * 2,                   \
                 Vtb + (size_t)row * SS + kk0 + coff);                       \
        }                                                                    \
        CP_COMMIT();                                                         \
    } while (0)

    // paired q-tiles: work(qb) + work(NQT-1-qb) = NQT+1 stages, constant
    #pragma unroll 1
    for (int pass = 0; pass < 2; pass++) {
        const int qb = pass ? (NQT - 1 - blockIdx.x) : blockIdx.x;
        const int q0 = qb * ABQ;

        uint32_t Qf[4][4];
        {
            const __half* qr0 = Qb + (size_t)(q0 + wrow + fr) * HD;
            const __half* qr1 = qr0 + 8 * HD;
            #pragma unroll
            for (int ks = 0; ks < 4; ks++) {
                Qf[ks][0] = *(const uint32_t*)(qr0 + 16 * ks + 2 * fk);
                Qf[ks][1] = *(const uint32_t*)(qr1 + 16 * ks + 2 * fk);
                Qf[ks][2] = *(const uint32_t*)(qr0 + 16 * ks + 8 + 2 * fk);
                Qf[ks][3] = *(const uint32_t*)(qr1 + 16 * ks + 8 + 2 * fk);
            }
        }

        float Oacc[8][4];
        #pragma unroll
        for (int nt = 0; nt < 8; nt++)
            #pragma unroll
            for (int r = 0; r < 4; r++) Oacc[nt][r] = 0.f;

        float m0 = -INFINITY, m1 = -INFINITY, l0 = 0.f, l1 = 0.f;

        const int r0g = q0 + wrow + fr;
        const int r1g = r0g + 8;
        const int nload = (q0 + ABQ) / LKEYS;

        A_ISSUE(0, 0);

        for (int lt = 0; lt < nload; lt++) {
            const int k0  = lt * LKEYS;
            const int buf = lt & 1;
            CP_WAIT0();
            __syncthreads();
            if (lt + 1 < nload) A_ISSUE(lt + 1, buf ^ 1);

            const bool active = (k0 <= q0 + wrow + 15);   // warp-uniform
            if (active) {
                const uint32_t kbase = sbase + (uint32_t)buf * (KSTAGE_H * 2);
                const uint32_t vbase = sbase + (uint32_t)((2 + buf) * KSTAGE_H) * 2;

                float Sacc[8][4];
                #pragma unroll
                for (int nt = 0; nt < 8; nt++)
                    #pragma unroll
                    for (int r = 0; r < 4; r++) Sacc[nt][r] = 0.f;

                #pragma unroll
                for (int ks = 0; ks < 4; ks++) {
                    uint32_t kf[4][4];
                    #pragma unroll
                    for (int p = 0; p < 4; p++)
                        LDSM4(kf[p][0], kf[p][1], kf[p][2], kf[p][3],
                              kbase + kvoff[p] + 32 * ks);
                    #pragma unroll
                    for (int nt = 0; nt < 8; nt++)
                        mma_f16(Sacc[nt],
                                Qf[ks][0], Qf[ks][1], Qf[ks][2], Qf[ks][3],
                                kf[nt >> 1][(nt & 1) * 2],
                                kf[nt >> 1][(nt & 1) * 2 + 1]);
                }

                const bool full = (k0 + 63 <= q0 + wrow);  // warp-uniform
                if (!full) {
                    #pragma unroll
                    for (int nt = 0; nt < 8; nt++) {
                        int c0 = k0 + nt * 8 + 2 * fk;
                        if (c0     > r0g) Sacc[nt][0] = -INFINITY;
                        if (c0 + 1 > r0g) Sacc[nt][1] = -INFINITY;
                        if (c0     > r1g) Sacc[nt][2] = -INFINITY;
                        if (c0 + 1 > r1g) Sacc[nt][3] = -INFINITY;
                    }
                }

                float mx0 = Sacc[0][0], mx1 = Sacc[0][2];
                #pragma unroll
                for (int nt = 0; nt < 8; nt++) {
                    mx0 = fmaxf(mx0, fmaxf(Sacc[nt][0], Sacc[nt][1]));
                    mx1 = fmaxf(mx1, fmaxf(Sacc[nt][2], Sacc[nt][3]));
                }
                mx0 = fmaxf(mx0, __shfl_xor_sync(0xFFFFFFFFu, mx0, 1));
                mx0 = fmaxf(mx0, __shfl_xor_sync(0xFFFFFFFFu, mx0, 2));
                mx1 = fmaxf(mx1, __shfl_xor_sync(0xFFFFFFFFu, mx1, 1));
                mx1 = fmaxf(mx1, __shfl_xor_sync(0xFFFFFFFFu, mx1, 2));

                float mn0 = fmaxf(m0, mx0 * tsc);
                float mn1 = fmaxf(m1, mx1 * tsc);
                float al0 = exp2f(m0 - mn0);
                float al1 = exp2f(m1 - mn1);
                m0 = mn0; m1 = mn1;

                uint32_t P01[8], P23[8];
                float ps0 = 0.f, ps1 = 0.f;
                #pragma unroll
                for (int nt = 0; nt < 8; nt++) {
                    float f0 = fmaf(Sacc[nt][0], tsc, -m0);
                    float f1 = fmaf(Sacc[nt][1], tsc, -m0);
                    float f2 = fmaf(Sacc[nt][2], tsc, -m1);
                    float f3 = fmaf(Sacc[nt][3], tsc, -m1);
                    __half2 e01 = __floats2half2_rn(f0, f1);
                    __half2 e23 = __floats2half2_rn(f2, f3);
                    uint32_t p01 = ex2_f16x2(*(const uint32_t*)&e01);
                    uint32_t p23 = ex2_f16x2(*(const uint32_t*)&e23);
                    P01[nt] = p01;
                    P23[nt] = p23;
                    float2 q01 = __half22float2(*(const __half2*)&p01);
                    float2 q23 = __half22float2(*(const __half2*)&p23);
                    ps0 += q01.x + q01.y;
                    ps1 += q23.x + q23.y;
                }
                ps0 += __shfl_xor_sync(0xFFFFFFFFu, ps0, 1);
                ps0 += __shfl_xor_sync(0xFFFFFFFFu, ps0, 2);
                ps1 += __shfl_xor_sync(0xFFFFFFFFu, ps1, 1);
                ps1 += __shfl_xor_sync(0xFFFFFFFFu, ps1, 2);
                l0 = l0 * al0 + ps0;
                l1 = l1 * al1 + ps1;

                if (!__all_sync(0xFFFFFFFFu, (al0 == 1.f) & (al1 == 1.f))) {
                    #pragma unroll
                    for (int nt = 0; nt < 8; nt++) {
                        Oacc[nt][0] *= al0; Oacc[nt][1] *= al0;
                        Oacc[nt][2] *= al1; Oacc[nt][3] *= al1;
                    }
                }

                #pragma unroll
                for (int kst = 0; kst < 4; kst++) {
                    uint32_t vf[4][4];
                    #pragma unroll
                    for (int p = 0; p < 4; p++)
                        LDSM4(vf[p][0], vf[p][1], vf[p][2], vf[p][3],
                              vbase + kvoff[p] + 32 * kst);
                    uint32_t a0 = P01[2 * kst];
                    uint32_t a1 = P23[2 * kst];
                    uint32_t a2 = P01[2 * kst + 1];
                    uint32_t a3 = P23[2 * kst + 1];
                    #pragma unroll
                    for (int nt = 0; nt < 8; nt++)
                        mma_f16(Oacc[nt], a0, a1, a2, a3,
                                vf[nt >> 1][(nt & 1) * 2],
                                vf[nt >> 1][(nt & 1) * 2 + 1]);
                }
            }
            __syncthreads();
        }

        // ---- epilogue: normalize, write fp16 [b, s, h*64+d] ----
        const int b = bh >> 4, h = bh & 15;
        const float inv0 = 1.f / l0;
        const float inv1 = 1.f / l1;
        __half* O0 = O + ((size_t)(b * SS + r0g)) * DM + h * HD;
        __half* O1 = O + ((size_t)(b * SS + r1g)) * DM + h * HD;
        #pragma unroll
        for (int nt = 0; nt < 8; nt++) {
            int d = nt * 8 + 2 * fk;
            *(__half2*)(O0 + d) = __floats2half2_rn(Oacc[nt][0] * inv0,
                                                    Oacc[nt][1] * inv0);
            *(__half2*)(O1 + d) = __floats2half2_rn(Oacc[nt][2] * inv1,
                                                    Oacc[nt][3] * inv1);
        }
        // pipeline fully drained; trailing __syncthreads in the last loop
        // iteration fences smem reuse for the next pass
    }
    #undef A_ISSUE
}

// ---------------------------------------------------------------------------
extern "C" void kernel_launch(void* const* d_in, const int* in_sizes, int n_in,
                              void* d_out, int out_size)
{
    const float* x  = (const float*)d_in[0];
    const float* Wq = (const float*)d_in[1];
    const float* bq = (const float*)d_in[2];
    const float* Wk = (const float*)d_in[3];
    const float* bk = (const float*)d_in[4];
    const float* Wv = (const float*)d_in[5];
    const float* bv = (const float*)d_in[6];
    const float* Wo = (const float*)d_in[7];
    const float* bo = (const float*)d_in[8];

    __half *xh, *wt, *qp, *kp, *vp, *ap;
    cudaGetSymbolAddress((void**)&xh, g_xh);
    cudaGetSymbolAddress((void**)&wt, g_Wt);
    cudaGetSymbolAddress((void**)&qp, g_Qh);
    cudaGetSymbolAddress((void**)&kp, g_Kh);
    cudaGetSymbolAddress((void**)&vp, g_Vt);
    cudaGetSymbolAddress((void**)&ap, g_att);

    cudaFuncSetAttribute(gemm_qkv,
        cudaFuncAttributeMaxDynamicSharedMemorySize, GEMM_SMEM);
    cudaFuncSetAttribute(gemm_o,
        cudaFuncAttributeMaxDynamicSharedMemorySize, GEMM_SMEM);
    cudaFuncSetAttribute(attn_h,
        cudaFuncAttributeMaxDynamicSharedMemorySize, ATTN_SMEM);

    // prep: one launch (weights transpose + x conversion)
    prep_all<<<dim3(DM * DM / 1024, 1, 8), 256>>>(x, Wq, Wk, Wv, Wo, xh, wt);

    dim3 gqkv(DM / 128, MROWS / 128, 3);   // (8, 32, 3)
    gemm_qkv<<<gqkv, 256, GEMM_SMEM>>>(xh, wt, bq, bk, bv, qp, kp, vp);

    attn_h<<<dim3(NQT / 2, BB * NH), 256, ATTN_SMEM>>>(qp, kp, vp, ap);

    dim3 go(DM / 128, MROWS / 128);        // (8, 32)
    gemm_o<<<go, 256, GEMM_SMEM>>>(ap, wt + (size_t)3*DM*DM, bo, (float*)d_out);
}